// round 16
// baseline (speedup 1.0000x reference)
#include <cuda_runtime.h>
#include <cuda_fp16.h>
#include <cstdint>
#include <cstddef>

// Problem constants
#define BB 4
#define NN 1024
#define DD 512
#define NHH 8
#define HH 64
#define TT 2
#define D2 1024   // 2*D

// ---------------- scratch (device globals; no allocation allowed) ----------------
__device__ float g_ie [BB*NN*D2];
__device__ float g_P  [BB*NN*D2];     // node_emb @ W_bot (iteration-invariant)
__device__ float g_xq [BB*NN*DD];
__device__ float g_xk [BB*NN*DD];
__device__ float g_xv [BB*NN*DD];
__device__ float g_tmp[BB*NN*DD];
__device__ float g_enc[BB*NN*DD];
__device__ float g_asrc[BB*NHH*9*NN];
__device__ float g_adst[BB*NHH*9*NN];
__device__ signed char g_cat[(size_t)BB*NN*NN];
__device__ float g_gates[BB*3*DD];
__device__ float g_hs[BB*D2];
__device__ float g_ms[BB*DD];
// fp16 planes (raw u16)
__device__ unsigned short g_nodeh[BB*NN*DD];
__device__ unsigned short g_ench [BB*NN*DD];
__device__ unsigned short g_ieh  [BB*NN*D2];
__device__ unsigned short g_xvh  [BB*NN*DD];
__device__ unsigned short g_Xh   [BB*NN*DD];
__device__ unsigned short g_Wdh  [D2*D2];       // [1024n][1024k]
__device__ unsigned short g_Wqkvh[3*DD*D2];     // [1536n][1024k]
__device__ unsigned short g_Wuh  [DD*D2];       // [512n][1024k]

// ---------------- helpers ----------------
__device__ __forceinline__ float warpSum(float v){
    #pragma unroll
    for (int o=16;o;o>>=1) v += __shfl_xor_sync(0xffffffffu, v, o);
    return v;
}
__device__ __forceinline__ float2 warpSum2(float2 v){
    #pragma unroll
    for (int o=16;o;o>>=1){
        v.x += __shfl_xor_sync(0xffffffffu, v.x, o);
        v.y += __shfl_xor_sync(0xffffffffu, v.y, o);
    }
    return v;
}
__device__ __forceinline__ float2 blockSum2(float2 v, float2* sh){
    int lane = threadIdx.x & 31, w = threadIdx.x >> 5;
    v = warpSum2(v);
    if (lane==0) sh[w] = v;
    __syncthreads();
    if (w==0){
        float2 x = (lane < (int)(blockDim.x>>5)) ? sh[lane] : make_float2(0.f,0.f);
        x = warpSum2(x);
        if (lane==0) sh[32] = x;
    }
    __syncthreads();
    float2 r = sh[32];
    __syncthreads();
    return r;
}
__device__ __forceinline__ uint32_t smem_u32(const void* p){
    uint32_t a;
    asm("{ .reg .u64 t; cvta.to.shared.u64 t, %1; cvt.u32.u64 %0, t; }" : "=r"(a) : "l"(p));
    return a;
}
__device__ __forceinline__ void cp16(uint32_t saddr, const void* gaddr){
    asm volatile("cp.async.cg.shared.global [%0], [%1], 16;" :: "r"(saddr), "l"(gaddr));
}
__device__ __forceinline__ void ldsm4(uint32_t* r, uint32_t addr){
    asm volatile("ldmatrix.sync.aligned.m8n8.x4.shared.b16 {%0,%1,%2,%3}, [%4];"
        : "=r"(r[0]), "=r"(r[1]), "=r"(r[2]), "=r"(r[3]) : "r"(addr));
}
__device__ __forceinline__ void ldsm4t(uint32_t* r, uint32_t addr){
    asm volatile("ldmatrix.sync.aligned.m8n8.x4.trans.shared.b16 {%0,%1,%2,%3}, [%4];"
        : "=r"(r[0]), "=r"(r[1]), "=r"(r[2]), "=r"(r[3]) : "r"(addr));
}
__device__ __forceinline__ void mma16816h(float* d, const uint32_t* a, const uint32_t* b){
    asm volatile("mma.sync.aligned.m16n8k16.row.col.f32.f16.f16.f32 "
        "{%0,%1,%2,%3}, {%4,%5,%6,%7}, {%8,%9}, {%0,%1,%2,%3};"
        : "+f"(d[0]), "+f"(d[1]), "+f"(d[2]), "+f"(d[3])
        : "r"(a[0]), "r"(a[1]), "r"(a[2]), "r"(a[3]), "r"(b[0]), "r"(b[1]));
}
__device__ __forceinline__ unsigned short f2h(float v){
    __half h = __float2half_rn(v);
    return *(unsigned short*)&h;
}
__device__ __forceinline__ uint32_t h2pack(float a, float b){
    uint32_t d;
    asm("{ .reg .f16 l, h; cvt.rn.f16.f32 l, %1; cvt.rn.f16.f32 h, %2; mov.b32 %0, {l, h}; }"
        : "=r"(d) : "f"(a), "f"(b));
    return d;
}

// ---------------- fp16 tensor-core GEMM (+ optional fp32 addend) ----------------
// C[M,N] = concat(A0|A1)[M,K] @ Bt[N,K]^T (+ Add[M,N]).
// CTA 64x128, BK=32, 4-stage cp.async, 512 threads (16 warps 2x8, warp tile 32x16,
// acc=16 regs). __launch_bounds__(512,2): <=64 regs -> 2 CTAs x 16 warps = 32
// warps/SM (was 24; probe showed issue=41% warp-starved).
#define STG_B 12288
#define GEMM_SMEM (4*STG_B)
__global__ __launch_bounds__(512, 2) void gemm_mma(
    const unsigned short* __restrict__ A0h, int lda0,
    const unsigned short* __restrict__ A1h, int lda1, int K0,
    const unsigned short* __restrict__ Bh_, int ldb,
    const float* __restrict__ Add,
    float* __restrict__ C0, float* __restrict__ C1, float* __restrict__ C2,
    int ldc, int nmod, int K)
{
    extern __shared__ char smem_buf[];
    uint32_t sb = smem_u32(smem_buf);
    int tid = threadIdx.x, lane = tid & 31, w = tid >> 5;
    int bm = blockIdx.y * 64, bn = blockIdx.x * 128;
    int mw = (w >> 3) * 32, nw = (w & 7) * 16;
    int KT = K >> 5;

    auto issue = [&](int t){
        int kt = t << 5;
        const unsigned short *Ah; int lda, kk;
        if (kt < K0){ Ah=A0h; lda=lda0; kk=kt; }
        else        { Ah=A1h; lda=lda1; kk=kt-K0; }
        uint32_t sbase = sb + (uint32_t)(t & 3) * STG_B;
        // A: 64 rows x 4 chunks = 256 loads (threads 0..255)
        if (tid < 256){
            int r = tid >> 2, c = tid & 3;
            uint32_t sa = sbase + r*64 + (uint32_t)((c ^ ((r>>1)&3)) << 4);
            cp16(sa, Ah + (size_t)(bm+r)*lda + kk + c*8);
        }
        // B: 128 rows x 4 chunks = 512 loads (1/thread)
        {
            int r = tid >> 2, c = tid & 3;
            uint32_t sa = sbase + 4096 + r*64 + (uint32_t)((c ^ ((r>>1)&3)) << 4);
            cp16(sa, Bh_ + (size_t)(bn+r)*ldb + kt + c*8);
        }
    };

    issue(0); asm volatile("cp.async.commit_group;");
    issue(1); asm volatile("cp.async.commit_group;");
    issue(2); asm volatile("cp.async.commit_group;");

    float acc[2][2][4];
    #pragma unroll
    for (int f=0;f<2;f++)
        #pragma unroll
        for (int n=0;n<2;n++)
            #pragma unroll
            for (int q=0;q<4;q++) acc[f][n][q]=0.f;

    for (int t=0; t<KT; t++){
        asm volatile("cp.async.wait_group 2;");
        __syncthreads();
        if (t+3 < KT) issue(t+3);
        asm volatile("cp.async.commit_group;");

        uint32_t st = sb + (uint32_t)(t & 3) * STG_B;
        #pragma unroll
        for (int ks=0; ks<2; ks++){
            int kc = ks*2 + (lane>>4);
            int rA = mw + (lane&15);
            int rB = nw + (lane&15);
            uint32_t a[2][4], bf[2][2];
            {
                uint32_t t4[4];
                ldsm4(t4, st + 4096 + rB*64 + ((kc ^ ((rB>>1)&3))<<4));
                bf[0][0]=t4[0]; bf[0][1]=t4[2];
                bf[1][0]=t4[1]; bf[1][1]=t4[3];
            }
            #pragma unroll
            for (int f=0; f<2; f++){
                int r = rA + f*16;
                ldsm4(a[f], st + r*64 + ((kc ^ ((r>>1)&3))<<4));
            }
            #pragma unroll
            for (int f=0;f<2;f++)
                #pragma unroll
                for (int n=0;n<2;n++) mma16816h(acc[f][n], a[f], bf[n]);
        }
    }
    asm volatile("cp.async.wait_group 0;");

    int sel = bn / nmod;
    float* C = (sel==0) ? C0 : ((sel==1) ? C1 : C2);
    int coff = bn % nmod;
    #pragma unroll
    for (int f=0;f<2;f++){
        int row = bm + mw + f*16 + (lane>>2);
        #pragma unroll
        for (int n=0;n<2;n++){
            int col = coff + nw + n*8 + (lane&3)*2;
            float2 v0 = make_float2(acc[f][n][0], acc[f][n][1]);
            float2 v1 = make_float2(acc[f][n][2], acc[f][n][3]);
            if (Add){
                float2 a0 = *(const float2*)&Add[(size_t)row*ldc + bn + nw + n*8 + (lane&3)*2];
                float2 a1 = *(const float2*)&Add[(size_t)(row+8)*ldc + bn + nw + n*8 + (lane&3)*2];
                v0.x += a0.x; v0.y += a0.y; v1.x += a1.x; v1.y += a1.y;
            }
            *(float2*)&C[(size_t)row*ldc + col]     = v0;
            *(float2*)&C[(size_t)(row+8)*ldc + col] = v1;
        }
    }
}

// ---------------- fp32 -> fp16 plane ----------------
__global__ __launch_bounds__(256) void split_plain(const float* __restrict__ X,
    unsigned short* __restrict__ H, int n)
{
    int i = blockIdx.x*256 + threadIdx.x;
    if (i < n) H[i] = f2h(X[i]);
}

// ---------------- transpose + fp16: W[K][N] fp32 -> T[N][K] fp16 ----------------
__global__ __launch_bounds__(256) void transpose_split(const float* __restrict__ W, int N,
    unsigned short* __restrict__ Th, int K)
{
    __shared__ float s[32][33];
    int n0 = blockIdx.x*32, k0 = blockIdx.y*32;
    int tx = threadIdx.x & 31, ty = threadIdx.x >> 5;
    #pragma unroll
    for (int i=0;i<4;i++)
        s[ty+8*i][tx] = W[(size_t)(k0+ty+8*i)*N + n0 + tx];
    __syncthreads();
    #pragma unroll
    for (int i=0;i<4;i++){
        int n = ty + 8*i;
        Th[(size_t)(n0+n)*K + k0 + tx] = f2h(s[tx][n]);
    }
}

// ---------------- category map (vectorized int4) ----------------
__global__ __launch_bounds__(256) void cat_kernel(const int* __restrict__ me,
                                                  const int* __restrict__ mts,
                                                  signed char* __restrict__ cat)
{
    size_t i4 = (size_t)blockIdx.x*256 + threadIdx.x;
    const size_t BNN4 = (size_t)BB*NN*NN/4;
    int4 e = ((const int4*)me)[i4];
    int c0 = e.x>0?0:-1, c1 = e.y>0?0:-1, c2 = e.z>0?0:-1, c3 = e.w>0?0:-1;
    #pragma unroll
    for (int k=0;k<8;k++){
        int4 m = ((const int4*)mts)[(size_t)k*BNN4 + i4];
        if (m.x>0) c0 = k+1;
        if (m.y>0) c1 = k+1;
        if (m.z>0) c2 = k+1;
        if (m.w>0) c3 = k+1;
    }
    uchar4 out = make_uchar4((unsigned char)(signed char)c0, (unsigned char)(signed char)c1,
                             (unsigned char)(signed char)c2, (unsigned char)(signed char)c3);
    ((uchar4*)cat)[i4] = out;
}

// ---------------- m_t pipeline: 3 wide-grid kernels (unrolled for MLP) ----------------
__global__ __launch_bounds__(256) void mtA(const float* __restrict__ q,
    const float* __restrict__ Wfc, float* __restrict__ hs)
{
    __shared__ float qs[DD];
    int b = blockIdx.x, c = blockIdx.y*256 + threadIdx.x;
    for (int i=threadIdx.x;i<DD;i+=256) qs[i] = q[b*DD+i];
    __syncthreads();
    float s=0.f;
    #pragma unroll 8
    for (int k=0;k<DD;k++) s += qs[k]*Wfc[(size_t)k*D2+c];
    hs[b*D2 + c] = s > 0.f ? s : expm1f(s);
}
__global__ __launch_bounds__(256) void mtB(const float* __restrict__ hs,
    const float* __restrict__ wdc, float* __restrict__ ms, int t)
{
    __shared__ float hsh[D2];
    int b = blockIdx.x, c = blockIdx.y*256 + threadIdx.x;
    for (int i=threadIdx.x;i<D2;i+=256) hsh[i] = hs[b*D2+i];
    __syncthreads();
    const float* wd = wdc + (size_t)t*D2*DD;
    float s=0.f;
    #pragma unroll 8
    for (int k=0;k<D2;k++) s += hsh[k]*wd[(size_t)k*DD+c];
    ms[b*DD + c] = s;
}
__global__ __launch_bounds__(256) void mtC(const float* __restrict__ ms,
    const float* __restrict__ Wqc, const float* __restrict__ Wkc, const float* __restrict__ Wvc,
    float* __restrict__ gates)
{
    __shared__ float msh[DD];
    int b = blockIdx.x;
    int sel = blockIdx.y >> 1;
    int c = (blockIdx.y & 1)*256 + threadIdx.x;
    for (int i=threadIdx.x;i<DD;i+=256) msh[i] = ms[b*DD+i];
    __syncthreads();
    const float* W = (sel==0) ? Wqc : ((sel==1) ? Wkc : Wvc);
    float s=0.f;
    #pragma unroll 8
    for (int k=0;k<DD;k++) s += msh[k]*W[(size_t)k*DD+c];
    gates[b*(3*DD) + sel*DD + c] = s;
}

// ---------------- LayerNorm (fused mean/var); optional fp16 plane out ----------------
__global__ __launch_bounds__(256) void ln_rows(const float* __restrict__ in,
    float* __restrict__ out, const float* __restrict__ gamma, const float* __restrict__ beta,
    const float* __restrict__ gate, int gate_pitch, int ncol, int rows_per_b,
    unsigned short* __restrict__ outH)
{
    __shared__ float2 sh[33];
    int row = blockIdx.x, tid = threadIdx.x;
    int b = row / rows_per_b;
    int nu = ncol >> 8;
    float x[4];
    const float* rp = in + (size_t)row*ncol;
    float2 s2 = make_float2(0.f, 0.f);
    for (int u=0;u<nu;u++){
        int c = tid + (u<<8);
        float v = rp[c];
        if (gate) v *= gate[b*gate_pitch + c];
        x[u]=v; s2.x+=v; s2.y+=v*v;
    }
    s2 = blockSum2(s2, sh);
    float mean = s2.x / (float)ncol;
    float var = s2.y / (float)ncol - mean*mean;
    float rstd = rsqrtf(fmaxf(var, 0.f) + 1e-12f);
    for (int u=0;u<nu;u++){
        int c = tid + (u<<8);
        float y = (x[u]-mean)*rstd*gamma[c] + beta[c];
        if (out) out[(size_t)row*ncol + c] = y;
        if (outH) outH[(size_t)row*ncol + c] = f2h(y);
    }
}

// ---------------- fused gated-LN(q) + gated-LN(k) + additive-attention dots ----------------
__global__ __launch_bounds__(256) void ln_qk_ascore(
    const float* __restrict__ xq_raw, const float* __restrict__ xk_raw,
    const float* __restrict__ gates,
    const float* __restrict__ ln_q_g, const float* __restrict__ ln_q_b,
    const float* __restrict__ ln_k_g, const float* __restrict__ ln_k_b,
    const float* __restrict__ Watt,
    float* __restrict__ asrc, float* __restrict__ adst)
{
    __shared__ float2 sh[33];
    __shared__ float qs[DD], ks[DD];
    int row = blockIdx.x, tid = threadIdx.x;
    int b = row >> 10, n = row & 1023;

    {
        const float* rp = xq_raw + (size_t)row*DD;
        const float* gp = gates + b*(3*DD);
        float x0 = rp[tid]       * gp[tid];
        float x1 = rp[tid + 256] * gp[tid + 256];
        float2 s2 = make_float2(x0 + x1, x0*x0 + x1*x1);
        s2 = blockSum2(s2, sh);
        float mean = s2.x / (float)DD;
        float var = s2.y / (float)DD - mean*mean;
        float rstd = rsqrtf(fmaxf(var, 0.f) + 1e-12f);
        qs[tid]     = (x0-mean)*rstd*ln_q_g[tid]     + ln_q_b[tid];
        qs[tid+256] = (x1-mean)*rstd*ln_q_g[tid+256] + ln_q_b[tid+256];
    }
    {
        const float* rp = xk_raw + (size_t)row*DD;
        const float* gp = gates + b*(3*DD) + DD;
        float x0 = rp[tid]       * gp[tid];
        float x1 = rp[tid + 256] * gp[tid + 256];
        float2 s2 = make_float2(x0 + x1, x0*x0 + x1*x1);
        s2 = blockSum2(s2, sh);
        float mean = s2.x / (float)DD;
        float var = s2.y / (float)DD - mean*mean;
        float rstd = rsqrtf(fmaxf(var, 0.f) + 1e-12f);
        ks[tid]     = (x0-mean)*rstd*ln_k_g[tid]     + ln_k_b[tid];
        ks[tid+256] = (x1-mean)*rstd*ln_k_g[tid+256] + ln_k_b[tid+256];
    }
    __syncthreads();

    if (tid < 144){
        int which = tid >= 72 ? 1 : 0;
        int t = which ? tid-72 : tid;
        int m = t / 8, h = t & 7;
        const float* w = Watt + m*(2*HH) + (which ? HH : 0);
        const float* xs = which ? ks : qs;
        float s = 0.f;
        #pragma unroll
        for (int d=0; d<HH; d++) s += xs[h*HH+d]*w[d];
        float* dst = which ? adst : asrc;
        dst[((size_t)(b*NHH+h)*9 + m)*NN + n] = s;
    }
}

// ---------------- fused attention: softmax (no-max; scores bounded) + P@V tensor cores ----------------
#define SMEM_ATTN ((9216 + 288 + 32)*4 + 32*136*2 + 128*72*2)
__global__ __launch_bounds__(256) void attn_kernel(
    const float* __restrict__ asrc, const float* __restrict__ adst,
    const signed char* __restrict__ cat, const unsigned short* __restrict__ xvh,
    unsigned short* __restrict__ Xh)
{
    extern __shared__ float smf[];
    float* adst_s = smf;
    float* asrc_s = adst_s + 9216;
    float* rowinv = asrc_s + 288;
    unsigned short* p_s = (unsigned short*)(rowinv + 32);
    unsigned short* v_s = p_s + 32*136;

    int it = blockIdx.x, h = blockIdx.y, b = blockIdx.z;
    int i0 = it*32, tid = threadIdx.x;

    const float* adst_g = adst + (size_t)(b*NHH+h)*9*NN;
    for (int i=tid;i<9216;i+=256) adst_s[i] = adst_g[i];
    const float* asrc_g = asrc + (size_t)(b*NHH+h)*9*NN;
    for (int i=tid;i<288;i+=256){ int r=i/9, m=i-r*9; asrc_s[i] = asrc_g[m*NN + i0 + r]; }
    __syncthreads();

    int lane = tid & 31, w = tid >> 5;
    const signed char* catb = cat + (size_t)b*NN*NN;

    // single-sweep softmax stats (scores bounded; exp without max-shift is safe and
    // softmax is shift-invariant, so result matches the reference exactly)
    for (int rr=0; rr<4; rr++){
        int ir = w*4 + rr;
        const signed char* crow = catb + (size_t)(i0+ir)*NN;
        float Z=0.f, S=0.f;
        for (int j=lane;j<NN;j+=32){
            int c = crow[j];
            float s = 0.f;
            if (c >= 0){ s = asrc_s[ir*9+c] + adst_s[c*NN+j]; s = s>0.f ? s : 0.01f*s; }
            float e = __expf(s);
            Z += e;
            if (c >= 0) S += e;
        }
        Z = warpSum(Z); S = warpSum(S);
        if (lane==0){
            float den = S + Z*1e-13f;
            rowinv[ir] = (S > 0.f) ? 1.f/den : 0.f;
        }
    }
    __syncthreads();

    int m0 = (w & 1) * 16;
    int n0 = (w >> 1) * 16;
    float acc0[4] = {0.f,0.f,0.f,0.f};
    float acc1[4] = {0.f,0.f,0.f,0.f};
    uint32_t pbase = smem_u32(p_s), vbase = smem_u32(v_s);

    for (int jt=0; jt<NN; jt+=128){
        for (int idx=tid; idx<32*128; idx+=256){
            int il = idx>>7, jj = idx&127;
            int c = catb[(size_t)(i0+il)*NN + jt + jj];
            float p = 0.f;
            if (c >= 0){
                float s = asrc_s[il*9+c] + adst_s[c*NN + jt + jj];
                s = s>0.f ? s : 0.01f*s;
                p = __expf(s) * rowinv[il];
            }
            p_s[il*136 + jj] = f2h(p);
        }
        for (int idx=tid; idx<2048; idx+=256){
            int jj = idx>>4, d4 = (idx&15)<<2;
            uint2 vv = *(const uint2*)&xvh[((size_t)(b*NN + jt + jj))*DD + h*HH + d4];
            *(uint2*)&v_s[jj*72 + d4] = vv;
        }
        __syncthreads();
        #pragma unroll
        for (int k0=0; k0<128; k0+=16){
            uint32_t a[4], bb[4];
            ldsm4 (a,  pbase + (uint32_t)(((m0 + (lane&15))*136 + k0 + (lane>>4)*8)*2));
            ldsm4t(bb, vbase + (uint32_t)(((k0 + (lane&15))*72 + n0 + (lane>>4)*8)*2));
            mma16816h(acc0, a, bb);
            mma16816h(acc1, a, bb+2);
        }
        __syncthreads();
    }

    {
        int row = i0 + m0 + (lane>>2);
        int col = n0 + (lane&3)*2;
        size_t base = ((size_t)(b*NN + row))*DD + h*HH + col;
        *(uint32_t*)&Xh[base]            = h2pack(acc0[0], acc0[1]);
        *(uint32_t*)&Xh[base + 8*DD]     = h2pack(acc0[2], acc0[3]);
        *(uint32_t*)&Xh[base + 8]        = h2pack(acc1[0], acc1[1]);
        *(uint32_t*)&Xh[base + 8*DD + 8] = h2pack(acc1[2], acc1[3]);
    }
}

// ---------------- host launcher ----------------
extern "C" void kernel_launch(void* const* d_in, const int* in_sizes, int n_in,
                              void* d_out, int out_size)
{
    const float* node_emb = (const float*)d_in[0];
    const float* qemb     = (const float*)d_in[1];
    const float* Wfc      = (const float*)d_in[2];
    const float* wdc      = (const float*)d_in[3];
    const float* dense_w  = (const float*)d_in[4];
    const float* ln_in_g  = (const float*)d_in[5];
    const float* ln_in_b  = (const float*)d_in[6];
    const float* Wqv      = (const float*)d_in[7];
    const float* Wkv      = (const float*)d_in[8];
    const float* Wvv      = (const float*)d_in[9];
    const float* Wqc      = (const float*)d_in[10];
    const float* Wkc      = (const float*)d_in[11];
    const float* Wvc      = (const float*)d_in[12];
    const float* ln_q_g   = (const float*)d_in[13];
    const float* ln_q_b   = (const float*)d_in[14];
    const float* ln_k_g   = (const float*)d_in[15];
    const float* ln_k_b   = (const float*)d_in[16];
    const float* ln_v_g   = (const float*)d_in[17];
    const float* ln_v_b   = (const float*)d_in[18];
    const float* Watt     = (const float*)d_in[19];
    const float* Wu       = (const float*)d_in[20];
    const float* ln_out_g = (const float*)d_in[21];
    const float* ln_out_b = (const float*)d_in[22];
    const int*   me       = (const int*)d_in[23];
    const int*   mts      = (const int*)d_in[24];

    float *p_ie, *p_P, *p_xq, *p_xk, *p_xv, *p_tmp, *p_enc, *p_asrc, *p_adst, *p_gates, *p_hs, *p_ms;
    signed char* p_cat;
    unsigned short *p_nodeh,*p_ench,*p_ieh,*p_xvh,*p_Xh,*p_Wdh,*p_Wqkvh,*p_Wuh;
    cudaGetSymbolAddress((void**)&p_ie,   g_ie);
    cudaGetSymbolAddress((void**)&p_P,    g_P);
    cudaGetSymbolAddress((void**)&p_xq,   g_xq);
    cudaGetSymbolAddress((void**)&p_xk,   g_xk);
    cudaGetSymbolAddress((void**)&p_xv,   g_xv);
    cudaGetSymbolAddress((void**)&p_tmp,  g_tmp);
    cudaGetSymbolAddress((void**)&p_enc,  g_enc);
    cudaGetSymbolAddress((void**)&p_asrc, g_asrc);
    cudaGetSymbolAddress((void**)&p_adst, g_adst);
    cudaGetSymbolAddress((void**)&p_gates,g_gates);
    cudaGetSymbolAddress((void**)&p_hs,   g_hs);
    cudaGetSymbolAddress((void**)&p_ms,   g_ms);
    cudaGetSymbolAddress((void**)&p_cat,  g_cat);
    cudaGetSymbolAddress((void**)&p_nodeh,g_nodeh);
    cudaGetSymbolAddress((void**)&p_ench, g_ench);
    cudaGetSymbolAddress((void**)&p_ieh,  g_ieh);
    cudaGetSymbolAddress((void**)&p_xvh,  g_xvh);
    cudaGetSymbolAddress((void**)&p_Xh,   g_Xh);
    cudaGetSymbolAddress((void**)&p_Wdh,  g_Wdh);
    cudaGetSymbolAddress((void**)&p_Wqkvh,g_Wqkvh);
    cudaGetSymbolAddress((void**)&p_Wuh,  g_Wuh);

    cudaFuncSetAttribute(attn_kernel, cudaFuncAttributeMaxDynamicSharedMemorySize, SMEM_ATTN);
    cudaFuncSetAttribute(gemm_mma, cudaFuncAttributeMaxDynamicSharedMemorySize, GEMM_SMEM);

    // ---- prep: launch index 3 = P-GEMM (ncu capture lands on index 3)
    split_plain<<<(BB*NN*DD)/256, 256>>>(node_emb, p_nodeh, BB*NN*DD);            // 0
    transpose_split<<<dim3(D2/32, D2/32), 256>>>(dense_w, D2, p_Wdh, D2);         // 1
    transpose_split<<<dim3(DD/32, D2/32), 256>>>(Wqv, DD, p_Wqkvh,           D2); // 2
    gemm_mma<<<dim3(D2/128, (BB*NN)/64), 512, GEMM_SMEM>>>(                       // 3  <- capture
        p_nodeh, DD, p_nodeh, DD, DD, p_Wdh + 512, D2, nullptr,
        p_P, p_P, p_P, D2, D2, DD);
    transpose_split<<<dim3(DD/32, D2/32), 256>>>(Wkv, DD, p_Wqkvh + DD*D2,   D2); // 4
    transpose_split<<<dim3(DD/32, D2/32), 256>>>(Wvv, DD, p_Wqkvh + 2*DD*D2, D2); // 5
    transpose_split<<<dim3(DD/32, D2/32), 256>>>(Wu, DD, p_Wuh, D2);              // 6
    cat_kernel<<<(BB*NN*NN)/1024, 256>>>(me, mts, p_cat);                         // 7

    for (int t=0; t<TT; t++){
        float* enc_out = (t == TT-1) ? (float*)d_out : p_enc;
        const unsigned short* eh = (t==0) ? p_nodeh : p_ench;

        // m_t pipeline (wide grids)
        mtA<<<dim3(BB, D2/256), 256>>>(qemb, Wfc, p_hs);
        mtB<<<dim3(BB, DD/256), 256>>>(p_hs, wdc, p_ms, t);
        mtC<<<dim3(BB, 6), 256>>>(p_ms, Wqc, Wkc, Wvc, p_gates);

        // ie = enc @ W_top + P ; LN (emit fp16 plane only)
        gemm_mma<<<dim3(D2/128, (BB*NN)/64), 512, GEMM_SMEM>>>(
            eh, DD, eh, DD, DD, p_Wdh, D2, p_P, p_ie, p_ie, p_ie, D2, D2, DD);
        ln_rows<<<BB*NN, 256>>>(p_ie, nullptr, ln_in_g, ln_in_b, nullptr, 0, D2, NN, p_ieh);

        // fused QKV projection: [4096,1024] @ [1024,1536]
        gemm_mma<<<dim3((3*DD)/128, (BB*NN)/64), 512, GEMM_SMEM>>>(
            p_ieh, D2, p_ieh, D2, D2, p_Wqkvh, D2, nullptr, p_xq, p_xk, p_xv, DD, DD, D2);

        // fused gated-LN(q,k) + ascore
        ln_qk_ascore<<<BB*NN, 256>>>(p_xq, p_xk, p_gates,
                                     ln_q_g, ln_q_b, ln_k_g, ln_k_b, Watt, p_asrc, p_adst);
        // v: gated LN, fp16 plane only
        ln_rows<<<BB*NN, 256>>>(p_xv, nullptr, ln_v_g, ln_v_b, p_gates + 2*DD, 3*DD, DD, NN, p_xvh);

        // fused masked-softmax attention + P@V (tensor cores, emits X fp16 plane)
        attn_kernel<<<dim3(NN/32, NHH, BB), 256, SMEM_ATTN>>>(p_asrc, p_adst, p_cat, p_xvh, p_Xh);

        // out = LN(concat(enc, X) @ W_u)
        gemm_mma<<<dim3(DD/128, (BB*NN)/64), 512, GEMM_SMEM>>>(
            eh, DD, p_Xh, DD, DD, p_Wuh, D2, nullptr, p_tmp, p_tmp, p_tmp, DD, DD, D2);
        ln_rows<<<BB*NN, 256>>>(p_tmp, enc_out, ln_out_g, ln_out_b, nullptr, 0, DD, NN, p_ench);
    }
}

// round 17
// speedup vs baseline: 1.0326x; 1.0326x over previous
#include <cuda_runtime.h>
#include <cuda_fp16.h>
#include <cstdint>
#include <cstddef>

// Problem constants
#define BB 4
#define NN 1024
#define DD 512
#define NHH 8
#define HH 64
#define TT 2
#define D2 1024   // 2*D

// ---------------- scratch (device globals; no allocation allowed) ----------------
__device__ float g_ie [BB*NN*D2];
__device__ float g_P  [BB*NN*D2];     // node_emb @ W_bot (iteration-invariant)
__device__ float g_xq [BB*NN*DD];
__device__ float g_xk [BB*NN*DD];
__device__ float g_xv [BB*NN*DD];
__device__ float g_tmp[BB*NN*DD];
__device__ float g_enc[BB*NN*DD];
__device__ float g_asrc[BB*NHH*9*NN];
__device__ float g_adst[BB*NHH*9*NN];
__device__ signed char g_cat[(size_t)BB*NN*NN];
__device__ float g_gates[BB*3*DD];
__device__ float g_hs[BB*D2];
__device__ float g_ms[BB*DD];
// fp16 planes (raw u16)
__device__ unsigned short g_nodeh[BB*NN*DD];
__device__ unsigned short g_ench [BB*NN*DD];
__device__ unsigned short g_ieh  [BB*NN*D2];
__device__ unsigned short g_xvh  [BB*NN*DD];
__device__ unsigned short g_Xh   [BB*NN*DD];
__device__ unsigned short g_Wdh  [D2*D2];       // [1024n][1024k]
__device__ unsigned short g_Wqkvh[3*DD*D2];     // [1536n][1024k]
__device__ unsigned short g_Wuh  [DD*D2];       // [512n][1024k]

// ---------------- helpers ----------------
__device__ __forceinline__ float warpSum(float v){
    #pragma unroll
    for (int o=16;o;o>>=1) v += __shfl_xor_sync(0xffffffffu, v, o);
    return v;
}
__device__ __forceinline__ float2 warpSum2(float2 v){
    #pragma unroll
    for (int o=16;o;o>>=1){
        v.x += __shfl_xor_sync(0xffffffffu, v.x, o);
        v.y += __shfl_xor_sync(0xffffffffu, v.y, o);
    }
    return v;
}
__device__ __forceinline__ float2 blockSum2(float2 v, float2* sh){
    int lane = threadIdx.x & 31, w = threadIdx.x >> 5;
    v = warpSum2(v);
    if (lane==0) sh[w] = v;
    __syncthreads();
    if (w==0){
        float2 x = (lane < (int)(blockDim.x>>5)) ? sh[lane] : make_float2(0.f,0.f);
        x = warpSum2(x);
        if (lane==0) sh[32] = x;
    }
    __syncthreads();
    float2 r = sh[32];
    __syncthreads();
    return r;
}
__device__ __forceinline__ uint32_t smem_u32(const void* p){
    uint32_t a;
    asm("{ .reg .u64 t; cvta.to.shared.u64 t, %1; cvt.u32.u64 %0, t; }" : "=r"(a) : "l"(p));
    return a;
}
__device__ __forceinline__ void cp16(uint32_t saddr, const void* gaddr){
    asm volatile("cp.async.cg.shared.global [%0], [%1], 16;" :: "r"(saddr), "l"(gaddr));
}
__device__ __forceinline__ void ldsm4(uint32_t* r, uint32_t addr){
    asm volatile("ldmatrix.sync.aligned.m8n8.x4.shared.b16 {%0,%1,%2,%3}, [%4];"
        : "=r"(r[0]), "=r"(r[1]), "=r"(r[2]), "=r"(r[3]) : "r"(addr));
}
__device__ __forceinline__ void ldsm4t(uint32_t* r, uint32_t addr){
    asm volatile("ldmatrix.sync.aligned.m8n8.x4.trans.shared.b16 {%0,%1,%2,%3}, [%4];"
        : "=r"(r[0]), "=r"(r[1]), "=r"(r[2]), "=r"(r[3]) : "r"(addr));
}
__device__ __forceinline__ void mma16816h(float* d, const uint32_t* a, const uint32_t* b){
    asm volatile("mma.sync.aligned.m16n8k16.row.col.f32.f16.f16.f32 "
        "{%0,%1,%2,%3}, {%4,%5,%6,%7}, {%8,%9}, {%0,%1,%2,%3};"
        : "+f"(d[0]), "+f"(d[1]), "+f"(d[2]), "+f"(d[3])
        : "r"(a[0]), "r"(a[1]), "r"(a[2]), "r"(a[3]), "r"(b[0]), "r"(b[1]));
}
__device__ __forceinline__ unsigned short f2h(float v){
    __half h = __float2half_rn(v);
    return *(unsigned short*)&h;
}
__device__ __forceinline__ uint32_t h2pack(float a, float b){
    uint32_t d;
    asm("{ .reg .f16 l, h; cvt.rn.f16.f32 l, %1; cvt.rn.f16.f32 h, %2; mov.b32 %0, {l, h}; }"
        : "=r"(d) : "f"(a), "f"(b));
    return d;
}

// ---------------- fp16 tensor-core GEMM (+ optional fp32 addend) ----------------
// C[M,N] = concat(A0|A1)[M,K] @ Bt[N,K]^T (+ Add[M,N]).
// CTA 64x128, BK=32, 4-stage cp.async, 256 threads (8 warps 2x4, warp tile 32x32).
// R15 champion config: __launch_bounds__(256,3) -> ~80 regs, 3 CTAs/SM = 24 warps.
// (R16's 32x16 tile raised occ but became ldmatrix-bound: L1 55%, tensor fell. Reverted.)
#define STG_B 12288
#define GEMM_SMEM (4*STG_B)
__global__ __launch_bounds__(256, 3) void gemm_mma(
    const unsigned short* __restrict__ A0h, int lda0,
    const unsigned short* __restrict__ A1h, int lda1, int K0,
    const unsigned short* __restrict__ Bh_, int ldb,
    const float* __restrict__ Add,
    float* __restrict__ C0, float* __restrict__ C1, float* __restrict__ C2,
    int ldc, int nmod, int K)
{
    extern __shared__ char smem_buf[];
    uint32_t sb = smem_u32(smem_buf);
    int tid = threadIdx.x, lane = tid & 31, w = tid >> 5;
    int bm = blockIdx.y * 64, bn = blockIdx.x * 128;
    int mw = (w >> 2) * 32, nw = (w & 3) * 32;
    int KT = K >> 5;

    auto issue = [&](int t){
        int kt = t << 5;
        const unsigned short *Ah; int lda, kk;
        if (kt < K0){ Ah=A0h; lda=lda0; kk=kt; }
        else        { Ah=A1h; lda=lda1; kk=kt-K0; }
        uint32_t sbase = sb + (uint32_t)(t & 3) * STG_B;
        // A: 64 rows x 4 chunks = 256 ids (1/thread)
        {
            int r = tid >> 2, c = tid & 3;
            uint32_t sa = sbase + r*64 + (uint32_t)((c ^ ((r>>1)&3)) << 4);
            cp16(sa, Ah + (size_t)(bm+r)*lda + kk + c*8);
        }
        // B: 128 rows x 4 chunks = 512 ids (2/thread)
        #pragma unroll
        for (int p=0;p<2;p++){
            int id = p*256 + tid;
            int r = id >> 2, c = id & 3;
            uint32_t sa = sbase + 4096 + r*64 + (uint32_t)((c ^ ((r>>1)&3)) << 4);
            cp16(sa, Bh_ + (size_t)(bn+r)*ldb + kt + c*8);
        }
    };

    issue(0); asm volatile("cp.async.commit_group;");
    issue(1); asm volatile("cp.async.commit_group;");
    issue(2); asm volatile("cp.async.commit_group;");

    float acc[2][4][4];
    #pragma unroll
    for (int f=0;f<2;f++)
        #pragma unroll
        for (int n=0;n<4;n++)
            #pragma unroll
            for (int q=0;q<4;q++) acc[f][n][q]=0.f;

    for (int t=0; t<KT; t++){
        asm volatile("cp.async.wait_group 2;");
        __syncthreads();
        if (t+3 < KT) issue(t+3);
        asm volatile("cp.async.commit_group;");

        uint32_t st = sb + (uint32_t)(t & 3) * STG_B;
        #pragma unroll
        for (int ks=0; ks<2; ks++){
            int kc = ks*2 + (lane>>4);
            int rA = mw + (lane&15);
            int rB = nw + (lane&15);
            uint32_t a[2][4], bf[4][2];
            #pragma unroll
            for (int gs=0; gs<2; gs++){
                int r = rB + gs*16;
                uint32_t t4[4];
                ldsm4(t4, st + 4096 + r*64 + ((kc ^ ((r>>1)&3))<<4));
                bf[2*gs][0]=t4[0]; bf[2*gs][1]=t4[2];
                bf[2*gs+1][0]=t4[1]; bf[2*gs+1][1]=t4[3];
            }
            #pragma unroll
            for (int f=0; f<2; f++){
                int r = rA + f*16;
                ldsm4(a[f], st + r*64 + ((kc ^ ((r>>1)&3))<<4));
            }
            #pragma unroll
            for (int f=0;f<2;f++)
                #pragma unroll
                for (int n=0;n<4;n++) mma16816h(acc[f][n], a[f], bf[n]);
        }
    }
    asm volatile("cp.async.wait_group 0;");

    int sel = bn / nmod;
    float* C = (sel==0) ? C0 : ((sel==1) ? C1 : C2);
    int coff = bn % nmod;
    #pragma unroll
    for (int f=0;f<2;f++){
        int row = bm + mw + f*16 + (lane>>2);
        #pragma unroll
        for (int n=0;n<4;n++){
            int col = coff + nw + n*8 + (lane&3)*2;
            float2 v0 = make_float2(acc[f][n][0], acc[f][n][1]);
            float2 v1 = make_float2(acc[f][n][2], acc[f][n][3]);
            if (Add){
                float2 a0 = *(const float2*)&Add[(size_t)row*ldc + bn + nw + n*8 + (lane&3)*2];
                float2 a1 = *(const float2*)&Add[(size_t)(row+8)*ldc + bn + nw + n*8 + (lane&3)*2];
                v0.x += a0.x; v0.y += a0.y; v1.x += a1.x; v1.y += a1.y;
            }
            *(float2*)&C[(size_t)row*ldc + col]     = v0;
            *(float2*)&C[(size_t)(row+8)*ldc + col] = v1;
        }
    }
}

// ---------------- fp32 -> fp16 plane ----------------
__global__ __launch_bounds__(256) void split_plain(const float* __restrict__ X,
    unsigned short* __restrict__ H, int n)
{
    int i = blockIdx.x*256 + threadIdx.x;
    if (i < n) H[i] = f2h(X[i]);
}

// ---------------- transpose + fp16: W[K][N] fp32 -> T[N][K] fp16 ----------------
__global__ __launch_bounds__(256) void transpose_split(const float* __restrict__ W, int N,
    unsigned short* __restrict__ Th, int K)
{
    __shared__ float s[32][33];
    int n0 = blockIdx.x*32, k0 = blockIdx.y*32;
    int tx = threadIdx.x & 31, ty = threadIdx.x >> 5;
    #pragma unroll
    for (int i=0;i<4;i++)
        s[ty+8*i][tx] = W[(size_t)(k0+ty+8*i)*N + n0 + tx];
    __syncthreads();
    #pragma unroll
    for (int i=0;i<4;i++){
        int n = ty + 8*i;
        Th[(size_t)(n0+n)*K + k0 + tx] = f2h(s[tx][n]);
    }
}

// ---------------- category map (vectorized int4) ----------------
__global__ __launch_bounds__(256) void cat_kernel(const int* __restrict__ me,
                                                  const int* __restrict__ mts,
                                                  signed char* __restrict__ cat)
{
    size_t i4 = (size_t)blockIdx.x*256 + threadIdx.x;
    const size_t BNN4 = (size_t)BB*NN*NN/4;
    int4 e = ((const int4*)me)[i4];
    int c0 = e.x>0?0:-1, c1 = e.y>0?0:-1, c2 = e.z>0?0:-1, c3 = e.w>0?0:-1;
    #pragma unroll
    for (int k=0;k<8;k++){
        int4 m = ((const int4*)mts)[(size_t)k*BNN4 + i4];
        if (m.x>0) c0 = k+1;
        if (m.y>0) c1 = k+1;
        if (m.z>0) c2 = k+1;
        if (m.w>0) c3 = k+1;
    }
    uchar4 out = make_uchar4((unsigned char)(signed char)c0, (unsigned char)(signed char)c1,
                             (unsigned char)(signed char)c2, (unsigned char)(signed char)c3);
    ((uchar4*)cat)[i4] = out;
}

// ---------------- m_t pipeline: 3 wide-grid kernels (unrolled for MLP) ----------------
__global__ __launch_bounds__(256) void mtA(const float* __restrict__ q,
    const float* __restrict__ Wfc, float* __restrict__ hs)
{
    __shared__ float qs[DD];
    int b = blockIdx.x, c = blockIdx.y*256 + threadIdx.x;
    for (int i=threadIdx.x;i<DD;i+=256) qs[i] = q[b*DD+i];
    __syncthreads();
    float s=0.f;
    #pragma unroll 8
    for (int k=0;k<DD;k++) s += qs[k]*Wfc[(size_t)k*D2+c];
    hs[b*D2 + c] = s > 0.f ? s : expm1f(s);
}
__global__ __launch_bounds__(256) void mtB(const float* __restrict__ hs,
    const float* __restrict__ wdc, float* __restrict__ ms, int t)
{
    __shared__ float hsh[D2];
    int b = blockIdx.x, c = blockIdx.y*256 + threadIdx.x;
    for (int i=threadIdx.x;i<D2;i+=256) hsh[i] = hs[b*D2+i];
    __syncthreads();
    const float* wd = wdc + (size_t)t*D2*DD;
    float s=0.f;
    #pragma unroll 8
    for (int k=0;k<D2;k++) s += hsh[k]*wd[(size_t)k*DD+c];
    ms[b*DD + c] = s;
}
__global__ __launch_bounds__(256) void mtC(const float* __restrict__ ms,
    const float* __restrict__ Wqc, const float* __restrict__ Wkc, const float* __restrict__ Wvc,
    float* __restrict__ gates)
{
    __shared__ float msh[DD];
    int b = blockIdx.x;
    int sel = blockIdx.y >> 1;
    int c = (blockIdx.y & 1)*256 + threadIdx.x;
    for (int i=threadIdx.x;i<DD;i+=256) msh[i] = ms[b*DD+i];
    __syncthreads();
    const float* W = (sel==0) ? Wqc : ((sel==1) ? Wkc : Wvc);
    float s=0.f;
    #pragma unroll 8
    for (int k=0;k<DD;k++) s += msh[k]*W[(size_t)k*DD+c];
    gates[b*(3*DD) + sel*DD + c] = s;
}

// ---------------- LayerNorm (fused mean/var); optional fp16 plane out ----------------
__global__ __launch_bounds__(256) void ln_rows(const float* __restrict__ in,
    float* __restrict__ out, const float* __restrict__ gamma, const float* __restrict__ beta,
    const float* __restrict__ gate, int gate_pitch, int ncol, int rows_per_b,
    unsigned short* __restrict__ outH)
{
    __shared__ float2 sh[33];
    int row = blockIdx.x, tid = threadIdx.x;
    int b = row / rows_per_b;
    int nu = ncol >> 8;
    float x[4];
    const float* rp = in + (size_t)row*ncol;
    float2 s2 = make_float2(0.f, 0.f);
    for (int u=0;u<nu;u++){
        int c = tid + (u<<8);
        float v = rp[c];
        if (gate) v *= gate[b*gate_pitch + c];
        x[u]=v; s2.x+=v; s2.y+=v*v;
    }
    s2 = blockSum2(s2, sh);
    float mean = s2.x / (float)ncol;
    float var = s2.y / (float)ncol - mean*mean;
    float rstd = rsqrtf(fmaxf(var, 0.f) + 1e-12f);
    for (int u=0;u<nu;u++){
        int c = tid + (u<<8);
        float y = (x[u]-mean)*rstd*gamma[c] + beta[c];
        if (out) out[(size_t)row*ncol + c] = y;
        if (outH) outH[(size_t)row*ncol + c] = f2h(y);
    }
}

// ---------------- fused gated-LN(q) + gated-LN(k) + additive-attention dots ----------------
__global__ __launch_bounds__(256) void ln_qk_ascore(
    const float* __restrict__ xq_raw, const float* __restrict__ xk_raw,
    const float* __restrict__ gates,
    const float* __restrict__ ln_q_g, const float* __restrict__ ln_q_b,
    const float* __restrict__ ln_k_g, const float* __restrict__ ln_k_b,
    const float* __restrict__ Watt,
    float* __restrict__ asrc, float* __restrict__ adst)
{
    __shared__ float2 sh[33];
    __shared__ float qs[DD], ks[DD];
    int row = blockIdx.x, tid = threadIdx.x;
    int b = row >> 10, n = row & 1023;

    {
        const float* rp = xq_raw + (size_t)row*DD;
        const float* gp = gates + b*(3*DD);
        float x0 = rp[tid]       * gp[tid];
        float x1 = rp[tid + 256] * gp[tid + 256];
        float2 s2 = make_float2(x0 + x1, x0*x0 + x1*x1);
        s2 = blockSum2(s2, sh);
        float mean = s2.x / (float)DD;
        float var = s2.y / (float)DD - mean*mean;
        float rstd = rsqrtf(fmaxf(var, 0.f) + 1e-12f);
        qs[tid]     = (x0-mean)*rstd*ln_q_g[tid]     + ln_q_b[tid];
        qs[tid+256] = (x1-mean)*rstd*ln_q_g[tid+256] + ln_q_b[tid+256];
    }
    {
        const float* rp = xk_raw + (size_t)row*DD;
        const float* gp = gates + b*(3*DD) + DD;
        float x0 = rp[tid]       * gp[tid];
        float x1 = rp[tid + 256] * gp[tid + 256];
        float2 s2 = make_float2(x0 + x1, x0*x0 + x1*x1);
        s2 = blockSum2(s2, sh);
        float mean = s2.x / (float)DD;
        float var = s2.y / (float)DD - mean*mean;
        float rstd = rsqrtf(fmaxf(var, 0.f) + 1e-12f);
        ks[tid]     = (x0-mean)*rstd*ln_k_g[tid]     + ln_k_b[tid];
        ks[tid+256] = (x1-mean)*rstd*ln_k_g[tid+256] + ln_k_b[tid+256];
    }
    __syncthreads();

    if (tid < 144){
        int which = tid >= 72 ? 1 : 0;
        int t = which ? tid-72 : tid;
        int m = t / 8, h = t & 7;
        const float* w = Watt + m*(2*HH) + (which ? HH : 0);
        const float* xs = which ? ks : qs;
        float s = 0.f;
        #pragma unroll
        for (int d=0; d<HH; d++) s += xs[h*HH+d]*w[d];
        float* dst = which ? adst : asrc;
        dst[((size_t)(b*NHH+h)*9 + m)*NN + n] = s;
    }
}

// ---------------- fused attention: softmax (no-max; scores bounded) + P@V tensor cores ----------------
#define SMEM_ATTN ((9216 + 288 + 32)*4 + 32*136*2 + 128*72*2)
__global__ __launch_bounds__(256) void attn_kernel(
    const float* __restrict__ asrc, const float* __restrict__ adst,
    const signed char* __restrict__ cat, const unsigned short* __restrict__ xvh,
    unsigned short* __restrict__ Xh)
{
    extern __shared__ float smf[];
    float* adst_s = smf;
    float* asrc_s = adst_s + 9216;
    float* rowinv = asrc_s + 288;
    unsigned short* p_s = (unsigned short*)(rowinv + 32);
    unsigned short* v_s = p_s + 32*136;

    int it = blockIdx.x, h = blockIdx.y, b = blockIdx.z;
    int i0 = it*32, tid = threadIdx.x;

    const float* adst_g = adst + (size_t)(b*NHH+h)*9*NN;
    for (int i=tid;i<9216;i+=256) adst_s[i] = adst_g[i];
    const float* asrc_g = asrc + (size_t)(b*NHH+h)*9*NN;
    for (int i=tid;i<288;i+=256){ int r=i/9, m=i-r*9; asrc_s[i] = asrc_g[m*NN + i0 + r]; }
    __syncthreads();

    int lane = tid & 31, w = tid >> 5;
    const signed char* catb = cat + (size_t)b*NN*NN;

    // single-sweep softmax stats (scores bounded; softmax shift-invariant)
    for (int rr=0; rr<4; rr++){
        int ir = w*4 + rr;
        const signed char* crow = catb + (size_t)(i0+ir)*NN;
        float Z=0.f, S=0.f;
        for (int j=lane;j<NN;j+=32){
            int c = crow[j];
            float s = 0.f;
            if (c >= 0){ s = asrc_s[ir*9+c] + adst_s[c*NN+j]; s = s>0.f ? s : 0.01f*s; }
            float e = __expf(s);
            Z += e;
            if (c >= 0) S += e;
        }
        Z = warpSum(Z); S = warpSum(S);
        if (lane==0){
            float den = S + Z*1e-13f;
            rowinv[ir] = (S > 0.f) ? 1.f/den : 0.f;
        }
    }
    __syncthreads();

    int m0 = (w & 1) * 16;
    int n0 = (w >> 1) * 16;
    float acc0[4] = {0.f,0.f,0.f,0.f};
    float acc1[4] = {0.f,0.f,0.f,0.f};
    uint32_t pbase = smem_u32(p_s), vbase = smem_u32(v_s);

    for (int jt=0; jt<NN; jt+=128){
        for (int idx=tid; idx<32*128; idx+=256){
            int il = idx>>7, jj = idx&127;
            int c = catb[(size_t)(i0+il)*NN + jt + jj];
            float p = 0.f;
            if (c >= 0){
                float s = asrc_s[il*9+c] + adst_s[c*NN + jt + jj];
                s = s>0.f ? s : 0.01f*s;
                p = __expf(s) * rowinv[il];
            }
            p_s[il*136 + jj] = f2h(p);
        }
        for (int idx=tid; idx<2048; idx+=256){
            int jj = idx>>4, d4 = (idx&15)<<2;
            uint2 vv = *(const uint2*)&xvh[((size_t)(b*NN + jt + jj))*DD + h*HH + d4];
            *(uint2*)&v_s[jj*72 + d4] = vv;
        }
        __syncthreads();
        #pragma unroll
        for (int k0=0; k0<128; k0+=16){
            uint32_t a[4], bb[4];
            ldsm4 (a,  pbase + (uint32_t)(((m0 + (lane&15))*136 + k0 + (lane>>4)*8)*2));
            ldsm4t(bb, vbase + (uint32_t)(((k0 + (lane&15))*72 + n0 + (lane>>4)*8)*2));
            mma16816h(acc0, a, bb);
            mma16816h(acc1, a, bb+2);
        }
        __syncthreads();
    }

    {
        int row = i0 + m0 + (lane>>2);
        int col = n0 + (lane&3)*2;
        size_t base = ((size_t)(b*NN + row))*DD + h*HH + col;
        *(uint32_t*)&Xh[base]            = h2pack(acc0[0], acc0[1]);
        *(uint32_t*)&Xh[base + 8*DD]     = h2pack(acc0[2], acc0[3]);
        *(uint32_t*)&Xh[base + 8]        = h2pack(acc1[0], acc1[1]);
        *(uint32_t*)&Xh[base + 8*DD + 8] = h2pack(acc1[2], acc1[3]);
    }
}

// ---------------- host launcher ----------------
extern "C" void kernel_launch(void* const* d_in, const int* in_sizes, int n_in,
                              void* d_out, int out_size)
{
    const float* node_emb = (const float*)d_in[0];
    const float* qemb     = (const float*)d_in[1];
    const float* Wfc      = (const float*)d_in[2];
    const float* wdc      = (const float*)d_in[3];
    const float* dense_w  = (const float*)d_in[4];
    const float* ln_in_g  = (const float*)d_in[5];
    const float* ln_in_b  = (const float*)d_in[6];
    const float* Wqv      = (const float*)d_in[7];
    const float* Wkv      = (const float*)d_in[8];
    const float* Wvv      = (const float*)d_in[9];
    const float* Wqc      = (const float*)d_in[10];
    const float* Wkc      = (const float*)d_in[11];
    const float* Wvc      = (const float*)d_in[12];
    const float* ln_q_g   = (const float*)d_in[13];
    const float* ln_q_b   = (const float*)d_in[14];
    const float* ln_k_g   = (const float*)d_in[15];
    const float* ln_k_b   = (const float*)d_in[16];
    const float* ln_v_g   = (const float*)d_in[17];
    const float* ln_v_b   = (const float*)d_in[18];
    const float* Watt     = (const float*)d_in[19];
    const float* Wu       = (const float*)d_in[20];
    const float* ln_out_g = (const float*)d_in[21];
    const float* ln_out_b = (const float*)d_in[22];
    const int*   me       = (const int*)d_in[23];
    const int*   mts      = (const int*)d_in[24];

    float *p_ie, *p_P, *p_xq, *p_xk, *p_xv, *p_tmp, *p_enc, *p_asrc, *p_adst, *p_gates, *p_hs, *p_ms;
    signed char* p_cat;
    unsigned short *p_nodeh,*p_ench,*p_ieh,*p_xvh,*p_Xh,*p_Wdh,*p_Wqkvh,*p_Wuh;
    cudaGetSymbolAddress((void**)&p_ie,   g_ie);
    cudaGetSymbolAddress((void**)&p_P,    g_P);
    cudaGetSymbolAddress((void**)&p_xq,   g_xq);
    cudaGetSymbolAddress((void**)&p_xk,   g_xk);
    cudaGetSymbolAddress((void**)&p_xv,   g_xv);
    cudaGetSymbolAddress((void**)&p_tmp,  g_tmp);
    cudaGetSymbolAddress((void**)&p_enc,  g_enc);
    cudaGetSymbolAddress((void**)&p_asrc, g_asrc);
    cudaGetSymbolAddress((void**)&p_adst, g_adst);
    cudaGetSymbolAddress((void**)&p_gates,g_gates);
    cudaGetSymbolAddress((void**)&p_hs,   g_hs);
    cudaGetSymbolAddress((void**)&p_ms,   g_ms);
    cudaGetSymbolAddress((void**)&p_cat,  g_cat);
    cudaGetSymbolAddress((void**)&p_nodeh,g_nodeh);
    cudaGetSymbolAddress((void**)&p_ench, g_ench);
    cudaGetSymbolAddress((void**)&p_ieh,  g_ieh);
    cudaGetSymbolAddress((void**)&p_xvh,  g_xvh);
    cudaGetSymbolAddress((void**)&p_Xh,   g_Xh);
    cudaGetSymbolAddress((void**)&p_Wdh,  g_Wdh);
    cudaGetSymbolAddress((void**)&p_Wqkvh,g_Wqkvh);
    cudaGetSymbolAddress((void**)&p_Wuh,  g_Wuh);

    cudaFuncSetAttribute(attn_kernel, cudaFuncAttributeMaxDynamicSharedMemorySize, SMEM_ATTN);
    cudaFuncSetAttribute(gemm_mma, cudaFuncAttributeMaxDynamicSharedMemorySize, GEMM_SMEM);

    // ---- prep: launch index 3 = P-GEMM (ncu capture lands on index 3)
    split_plain<<<(BB*NN*DD)/256, 256>>>(node_emb, p_nodeh, BB*NN*DD);            // 0
    transpose_split<<<dim3(D2/32, D2/32), 256>>>(dense_w, D2, p_Wdh, D2);         // 1
    transpose_split<<<dim3(DD/32, D2/32), 256>>>(Wqv, DD, p_Wqkvh,           D2); // 2
    gemm_mma<<<dim3(D2/128, (BB*NN)/64), 256, GEMM_SMEM>>>(                       // 3  <- capture
        p_nodeh, DD, p_nodeh, DD, DD, p_Wdh + 512, D2, nullptr,
        p_P, p_P, p_P, D2, D2, DD);
    transpose_split<<<dim3(DD/32, D2/32), 256>>>(Wkv, DD, p_Wqkvh + DD*D2,   D2); // 4
    transpose_split<<<dim3(DD/32, D2/32), 256>>>(Wvv, DD, p_Wqkvh + 2*DD*D2, D2); // 5
    transpose_split<<<dim3(DD/32, D2/32), 256>>>(Wu, DD, p_Wuh, D2);              // 6
    cat_kernel<<<(BB*NN*NN)/1024, 256>>>(me, mts, p_cat);                         // 7

    for (int t=0; t<TT; t++){
        float* enc_out = (t == TT-1) ? (float*)d_out : p_enc;
        const unsigned short* eh = (t==0) ? p_nodeh : p_ench;

        // m_t pipeline (wide grids)
        mtA<<<dim3(BB, D2/256), 256>>>(qemb, Wfc, p_hs);
        mtB<<<dim3(BB, DD/256), 256>>>(p_hs, wdc, p_ms, t);
        mtC<<<dim3(BB, 6), 256>>>(p_ms, Wqc, Wkc, Wvc, p_gates);

        // ie = enc @ W_top + P ; LN (emit fp16 plane only)
        gemm_mma<<<dim3(D2/128, (BB*NN)/64), 256, GEMM_SMEM>>>(
            eh, DD, eh, DD, DD, p_Wdh, D2, p_P, p_ie, p_ie, p_ie, D2, D2, DD);
        ln_rows<<<BB*NN, 256>>>(p_ie, nullptr, ln_in_g, ln_in_b, nullptr, 0, D2, NN, p_ieh);

        // fused QKV projection: [4096,1024] @ [1024,1536]
        gemm_mma<<<dim3((3*DD)/128, (BB*NN)/64), 256, GEMM_SMEM>>>(
            p_ieh, D2, p_ieh, D2, D2, p_Wqkvh, D2, nullptr, p_xq, p_xk, p_xv, DD, DD, D2);

        // fused gated-LN(q,k) + ascore
        ln_qk_ascore<<<BB*NN, 256>>>(p_xq, p_xk, p_gates,
                                     ln_q_g, ln_q_b, ln_k_g, ln_k_b, Watt, p_asrc, p_adst);
        // v: gated LN, fp16 plane only
        ln_rows<<<BB*NN, 256>>>(p_xv, nullptr, ln_v_g, ln_v_b, p_gates + 2*DD, 3*DD, DD, NN, p_xvh);

        // fused masked-softmax attention + P@V (tensor cores, emits X fp16 plane)
        attn_kernel<<<dim3(NN/32, NHH, BB), 256, SMEM_ATTN>>>(p_asrc, p_adst, p_cat, p_xvh, p_Xh);

        // out = LN(concat(enc, X) @ W_u)
        gemm_mma<<<dim3(DD/128, (BB*NN)/64), 256, GEMM_SMEM>>>(
            eh, DD, p_Xh, DD, DD, p_Wuh, D2, nullptr, p_tmp, p_tmp, p_tmp, DD, DD, D2);
        ln_rows<<<BB*NN, 256>>>(p_tmp, enc_out, ln_out_g, ln_out_b, nullptr, 0, DD, NN, p_ench);
    }
}